// round 16
// baseline (speedup 1.0000x reference)
#include <cuda_runtime.h>
#include <cuda_bf16.h>
#include <cstdint>

#define DD 128
#define MAXN 50000
#define MAXE 800000

// ---------------- device scratch ----------------
__device__ float g_mean[(size_t)MAXN * DD];
__device__ float g_tmp[(size_t)MAXN * DD];     // self-path partial: h @ Wr + b
__device__ float g_ha[(size_t)MAXN * DD];
__device__ float g_hb[(size_t)MAXN * DD];
__device__ float g_invdeg[MAXN];
__device__ int   g_degi[MAXN];
__device__ int   g_rowstart[MAXN + 1];
__device__ int   g_cursor[MAXN];
__device__ int   g_csr[MAXE];
// pre-split, transposed weights: [mat][n*128 + k], mat = 2*layer + {0:Wl,1:Wr}
__device__ __nv_bfloat16 g_wthi[6 * 128 * 128];
__device__ __nv_bfloat16 g_wtlo[6 * 128 * 128];

// ---------------- helpers ----------------
static __device__ __forceinline__ uint32_t smem_u32(const void* p) {
    uint32_t a;
    asm("{ .reg .u64 t; cvta.to.shared.u64 t, %1; cvt.u32.u64 %0, t; }" : "=r"(a) : "l"(p));
    return a;
}
static __device__ __forceinline__ void ldsm_x4(uint32_t* r, uint32_t addr) {
    asm volatile("ldmatrix.sync.aligned.m8n8.x4.shared.b16 {%0,%1,%2,%3}, [%4];"
                 : "=r"(r[0]), "=r"(r[1]), "=r"(r[2]), "=r"(r[3]) : "r"(addr));
}
static __device__ __forceinline__ void mma16816(float* c, const uint32_t* a, const uint32_t* b) {
    asm volatile("mma.sync.aligned.m16n8k16.row.col.f32.bf16.bf16.f32 "
                 "{%0,%1,%2,%3}, {%4,%5,%6,%7}, {%8,%9}, {%0,%1,%2,%3};"
                 : "+f"(c[0]), "+f"(c[1]), "+f"(c[2]), "+f"(c[3])
                 : "r"(a[0]), "r"(a[1]), "r"(a[2]), "r"(a[3]), "r"(b[0]), "r"(b[1]));
}

// ---------------- CSR construction (degi zeroed by cudaMemsetAsync) ----------------
__global__ void count_deg(const int* __restrict__ ei, int E) {
    int e = blockIdx.x * blockDim.x + threadIdx.x;
    if (e < E) atomicAdd(&g_degi[ei[E + e]], 1);
}
// exclusive scan of degi -> rowstart, cursor (=exclusive), invdeg; 1024 thr, 4/thread
__global__ void scan_kernel(int n) {
    __shared__ int warp_sums[32];
    __shared__ int s_carry;
    int t = threadIdx.x, lane = t & 31, w = t >> 5;
    if (t == 0) { g_rowstart[0] = 0; s_carry = 0; }
    __syncthreads();
    for (int base = 0; base < n; base += 4096) {
        int i0 = base + t * 4;
        int v0 = 0, v1 = 0, v2 = 0, v3 = 0;
        if (i0 + 3 < n) {
            int4 q = *(const int4*)(g_degi + i0);
            v0 = q.x; v1 = q.y; v2 = q.z; v3 = q.w;
        } else {
            if (i0 < n)     v0 = g_degi[i0];
            if (i0 + 1 < n) v1 = g_degi[i0 + 1];
            if (i0 + 2 < n) v2 = g_degi[i0 + 2];
            if (i0 + 3 < n) v3 = g_degi[i0 + 3];
        }
        int v = v0 + v1 + v2 + v3;
        int x = v;
        #pragma unroll
        for (int off = 1; off < 32; off <<= 1) {
            int y = __shfl_up_sync(0xFFFFFFFFu, x, off);
            if (lane >= off) x += y;
        }
        if (lane == 31) warp_sums[w] = x;
        __syncthreads();
        if (w == 0) {
            int s = warp_sums[lane];
            #pragma unroll
            for (int off = 1; off < 32; off <<= 1) {
                int y = __shfl_up_sync(0xFFFFFFFFu, s, off);
                if (lane >= off) s += y;
            }
            warp_sums[lane] = s;
        }
        __syncthreads();
        int incl = x + (w > 0 ? warp_sums[w - 1] : 0) + s_carry;
        int excl = incl - v;
        int p0 = excl + v0, p1 = p0 + v1, p2 = p1 + v2, p3 = p2 + v3;
        if (i0 < n)     { g_rowstart[i0 + 1] = p0; g_cursor[i0]     = excl; g_invdeg[i0]     = 1.0f / (float)(v0 > 0 ? v0 : 1); }
        if (i0 + 1 < n) { g_rowstart[i0 + 2] = p1; g_cursor[i0 + 1] = p0;   g_invdeg[i0 + 1] = 1.0f / (float)(v1 > 0 ? v1 : 1); }
        if (i0 + 2 < n) { g_rowstart[i0 + 3] = p2; g_cursor[i0 + 2] = p1;   g_invdeg[i0 + 2] = 1.0f / (float)(v2 > 0 ? v2 : 1); }
        if (i0 + 3 < n) { g_rowstart[i0 + 4] = p3; g_cursor[i0 + 3] = p2;   g_invdeg[i0 + 3] = 1.0f / (float)(v3 > 0 ? v3 : 1); }
        __syncthreads();
        if (t == 1023) s_carry = incl;
        __syncthreads();
    }
}
__global__ void fill_csr(const int* __restrict__ ei, int E) {
    int e = blockIdx.x * blockDim.x + threadIdx.x;
    if (e < E) {
        int s = ei[e];
        int d = ei[E + e];
        int p = atomicAdd(&g_cursor[d], 1);   // cursor pre-seeded with rowstart
        g_csr[p] = s;
    }
}

// ---------------- weight pre-split (transpose + bf16 hi/lo) — side stream ----------------
__global__ void wsplit_kernel(const float* w0, const float* w1, const float* w2,
                              const float* w3, const float* w4, const float* w5) {
    int id = blockIdx.x * blockDim.x + threadIdx.x;
    if (id >= 6 * 128 * 128) return;
    int mat = id >> 14, rem = id & 16383;
    int nn = rem >> 7, kk = rem & 127;
    const float* w;
    switch (mat) {
        case 0: w = w0; break; case 1: w = w1; break; case 2: w = w2; break;
        case 3: w = w3; break; case 4: w = w4; break; default: w = w5; break;
    }
    float v = w[kk * 128 + nn];           // transpose: wt[n][k] = w[k][n]
    __nv_bfloat16 hi = __float2bfloat16(v);
    g_wthi[id] = hi;
    g_wtlo[id] = __float2bfloat16(v - __bfloat162float(hi));
}

// ---------------- aggregation: warp per node, gather-only (proven config) ----------------
__global__ void aggregate_kernel(const float* __restrict__ hin, int n) {
    int gw = (blockIdx.x * blockDim.x + threadIdx.x) >> 5;
    int lane = threadIdx.x & 31;
    if (gw >= n) return;
    int s0 = g_rowstart[gw], s1 = g_rowstart[gw + 1];
    float ax = 0.f, ay = 0.f, az = 0.f, aw = 0.f;
    int i = s0;
    for (; i + 4 <= s1; i += 4) {
        int e0 = g_csr[i], e1 = g_csr[i + 1], e2 = g_csr[i + 2], e3 = g_csr[i + 3];
        float4 v0 = *(const float4*)(hin + (size_t)e0 * DD + lane * 4);
        float4 v1 = *(const float4*)(hin + (size_t)e1 * DD + lane * 4);
        float4 v2 = *(const float4*)(hin + (size_t)e2 * DD + lane * 4);
        float4 v3 = *(const float4*)(hin + (size_t)e3 * DD + lane * 4);
        ax += (v0.x + v1.x) + (v2.x + v3.x);
        ay += (v0.y + v1.y) + (v2.y + v3.y);
        az += (v0.z + v1.z) + (v2.z + v3.z);
        aw += (v0.w + v1.w) + (v2.w + v3.w);
    }
    for (; i < s1; i++) {
        int e0 = g_csr[i];
        float4 v = *(const float4*)(hin + (size_t)e0 * DD + lane * 4);
        ax += v.x; ay += v.y; az += v.z; aw += v.w;
    }
    float inv = g_invdeg[gw];
    float4 r;
    r.x = ax * inv; r.y = ay * inv; r.z = az * inv; r.w = aw * inv;
    *(float4*)(g_mean + (size_t)gw * DD + lane * 4) = r;
}

// ---------------- single-chunk split-bf16 GEMM machinery ----------------
// 3-term split: A@B ~= Ahi@Bhi + Ahi@Blo + Alo@Bhi, K=128, CTA 128x128, 8 warps.
#define KPAD_B 272
#define A_HI 0
#define A_LO (128 * KPAD_B)
#define B_HI (2 * 128 * KPAD_B)
#define B_LO (3 * 128 * KPAD_B)
#define CMB_SMEM (4 * 128 * KPAD_B)      // 139,264 bytes

// stage A (fp32 src -> bf16 hi/lo planes) + B (pre-split weights), then MMA into acc
static __device__ __forceinline__ void gemm_core(
    char* smem, uint32_t sb, const float* __restrict__ src,
    const __nv_bfloat16* __restrict__ bh, const __nv_bfloat16* __restrict__ bl,
    int row0, int n, int tid, float acc[2][8][4],
    int a_row, int a_koff, int b_nrow, int b_koff)
{
    for (int idx = tid; idx < 4096; idx += 256) {
        int r = idx >> 5, kq = idx & 31;
        int row = row0 + r;
        float4 v = {0.f, 0.f, 0.f, 0.f};
        if (row < n) v = *(const float4*)(src + (size_t)row * DD + kq * 4);
        __nv_bfloat16 hx = __float2bfloat16(v.x), hy = __float2bfloat16(v.y);
        __nv_bfloat16 hz = __float2bfloat16(v.z), hw = __float2bfloat16(v.w);
        __nv_bfloat162 h01, h23, l01, l23;
        h01.x = hx; h01.y = hy; h23.x = hz; h23.y = hw;
        l01.x = __float2bfloat16(v.x - __bfloat162float(hx));
        l01.y = __float2bfloat16(v.y - __bfloat162float(hy));
        l23.x = __float2bfloat16(v.z - __bfloat162float(hz));
        l23.y = __float2bfloat16(v.w - __bfloat162float(hw));
        uint2 hp, lp;
        hp.x = *(uint32_t*)&h01; hp.y = *(uint32_t*)&h23;
        lp.x = *(uint32_t*)&l01; lp.y = *(uint32_t*)&l23;
        *(uint2*)(smem + A_HI + r * KPAD_B + kq * 8) = hp;
        *(uint2*)(smem + A_LO + r * KPAD_B + kq * 8) = lp;
    }
    for (int idx = tid; idx < 2048; idx += 256) {
        int nr = idx >> 4, kg = idx & 15;
        *(uint4*)(smem + B_HI + nr * KPAD_B + kg * 16) = *(const uint4*)(bh + nr * 128 + kg * 8);
        *(uint4*)(smem + B_LO + nr * KPAD_B + kg * 16) = *(const uint4*)(bl + nr * 128 + kg * 8);
    }
    __syncthreads();
    #pragma unroll
    for (int ks = 0; ks < 8; ks++) {
        int k0 = ks * 16;
        uint32_t aF[2][2][4];
        #pragma unroll
        for (int p = 0; p < 2; p++)
            #pragma unroll
            for (int mi = 0; mi < 2; mi++)
                ldsm_x4(aF[p][mi],
                        sb + (p ? A_LO : A_HI) + (a_row + mi * 16) * KPAD_B + (k0 + a_koff) * 2);
        uint32_t bF[2][4][4];
        #pragma unroll
        for (int p = 0; p < 2; p++)
            #pragma unroll
            for (int gj = 0; gj < 4; gj++)
                ldsm_x4(bF[p][gj],
                        sb + (p ? B_LO : B_HI) + (b_nrow + gj * 16) * KPAD_B + (k0 + b_koff) * 2);
        #pragma unroll
        for (int mi = 0; mi < 2; mi++)
            #pragma unroll
            for (int nj = 0; nj < 8; nj++) {
                int gj = nj >> 1, s = (nj & 1) * 2;
                mma16816(acc[mi][nj], aF[0][mi], &bF[0][gj][s]);
                mma16816(acc[mi][nj], aF[0][mi], &bF[1][gj][s]);
                mma16816(acc[mi][nj], aF[1][mi], &bF[0][gj][s]);
            }
    }
}

// self path: tmp = h @ Wr + b   (side stream; overlaps aggregate)
__global__ __launch_bounds__(256, 1) void gemm_self(
    const float* __restrict__ h,
    const __nv_bfloat16* __restrict__ bh, const __nv_bfloat16* __restrict__ bl,
    const float* __restrict__ bias, float* __restrict__ tmp, int n)
{
    extern __shared__ char smem[];
    uint32_t sb = smem_u32(smem);
    int tid = threadIdx.x, wid = tid >> 5, lane = tid & 31;
    int row0 = blockIdx.x * 128;
    int wR = wid >> 1, wC = wid & 1;
    float acc[2][8][4];
    #pragma unroll
    for (int mi = 0; mi < 2; mi++)
        #pragma unroll
        for (int nj = 0; nj < 8; nj++)
            #pragma unroll
            for (int q = 0; q < 4; q++) acc[mi][nj][q] = 0.f;
    int a_row = wR * 32 + (lane & 15), a_koff = (lane >> 4) * 8;
    int b_nrow = wC * 64 + (lane & 7) + ((lane >> 4) << 3), b_koff = ((lane >> 3) & 1) * 8;

    gemm_core(smem, sb, h, bh, bl, row0, n, tid, acc, a_row, a_koff, b_nrow, b_koff);

    #pragma unroll
    for (int mi = 0; mi < 2; mi++) {
        int r0a = row0 + wR * 32 + mi * 16 + (lane >> 2);
        #pragma unroll
        for (int nj = 0; nj < 8; nj++) {
            int col = wC * 64 + nj * 8 + (lane & 3) * 2;
            float2 bb = *(const float2*)(bias + col);
            float2 v0, v1;
            v0.x = acc[mi][nj][0] + bb.x; v0.y = acc[mi][nj][1] + bb.y;
            v1.x = acc[mi][nj][2] + bb.x; v1.y = acc[mi][nj][3] + bb.y;
            if (r0a < n)     *(float2*)(tmp + (size_t)r0a * DD + col) = v0;
            if (r0a + 8 < n) *(float2*)(tmp + (size_t)(r0a + 8) * DD + col) = v1;
        }
    }
}

// mean path: out = mean @ Wl + tmp (+ReLU)
template <bool RELU>
__global__ __launch_bounds__(256, 1) void gemm_mean(
    const __nv_bfloat16* __restrict__ bh, const __nv_bfloat16* __restrict__ bl,
    const float* __restrict__ tmp, float* __restrict__ out, int n)
{
    extern __shared__ char smem[];
    uint32_t sb = smem_u32(smem);
    int tid = threadIdx.x, wid = tid >> 5, lane = tid & 31;
    int row0 = blockIdx.x * 128;
    int wR = wid >> 1, wC = wid & 1;
    float acc[2][8][4];
    #pragma unroll
    for (int mi = 0; mi < 2; mi++)
        #pragma unroll
        for (int nj = 0; nj < 8; nj++)
            #pragma unroll
            for (int q = 0; q < 4; q++) acc[mi][nj][q] = 0.f;
    int a_row = wR * 32 + (lane & 15), a_koff = (lane >> 4) * 8;
    int b_nrow = wC * 64 + (lane & 7) + ((lane >> 4) << 3), b_koff = ((lane >> 3) & 1) * 8;

    gemm_core(smem, sb, g_mean, bh, bl, row0, n, tid, acc, a_row, a_koff, b_nrow, b_koff);

    #pragma unroll
    for (int mi = 0; mi < 2; mi++) {
        int r0a = row0 + wR * 32 + mi * 16 + (lane >> 2);
        #pragma unroll
        for (int nj = 0; nj < 8; nj++) {
            int col = wC * 64 + nj * 8 + (lane & 3) * 2;
            float2 v0, v1;
            if (r0a < n) {
                float2 t0 = *(const float2*)(tmp + (size_t)r0a * DD + col);
                v0.x = acc[mi][nj][0] + t0.x; v0.y = acc[mi][nj][1] + t0.y;
                if (RELU) { v0.x = fmaxf(v0.x, 0.f); v0.y = fmaxf(v0.y, 0.f); }
                *(float2*)(out + (size_t)r0a * DD + col) = v0;
            }
            if (r0a + 8 < n) {
                float2 t1 = *(const float2*)(tmp + (size_t)(r0a + 8) * DD + col);
                v1.x = acc[mi][nj][2] + t1.x; v1.y = acc[mi][nj][3] + t1.y;
                if (RELU) { v1.x = fmaxf(v1.x, 0.f); v1.y = fmaxf(v1.y, 0.f); }
                *(float2*)(out + (size_t)(r0a + 8) * DD + col) = v1;
            }
        }
    }
}

// ---------------- launch: fork-join overlap of self-GEMM with CSR/aggregate ----------------
extern "C" void kernel_launch(void* const* d_in, const int* in_sizes, int n_in,
                              void* d_out, int out_size) {
    const float* x   = (const float*)d_in[0];
    const int*   ei  = (const int*)d_in[1];
    const float* wl0 = (const float*)d_in[2];
    const float* wr0 = (const float*)d_in[3];
    const float* b0  = (const float*)d_in[4];
    const float* wl1 = (const float*)d_in[5];
    const float* wr1 = (const float*)d_in[6];
    const float* b1  = (const float*)d_in[7];
    const float* wl2 = (const float*)d_in[8];
    const float* wr2 = (const float*)d_in[9];
    const float* b2  = (const float*)d_in[10];
    float* out = (float*)d_out;

    int n = in_sizes[0] / DD;
    int E = in_sizes[1] / 2;

    float *tmp_p, *ha_p, *hb_p;
    int* degi_p;
    __nv_bfloat16 *wthi_p, *wtlo_p;
    cudaGetSymbolAddress((void**)&tmp_p, g_tmp);
    cudaGetSymbolAddress((void**)&ha_p, g_ha);
    cudaGetSymbolAddress((void**)&hb_p, g_hb);
    cudaGetSymbolAddress((void**)&degi_p, g_degi);
    cudaGetSymbolAddress((void**)&wthi_p, g_wthi);
    cudaGetSymbolAddress((void**)&wtlo_p, g_wtlo);

    cudaFuncSetAttribute((const void*)gemm_self,
                         cudaFuncAttributeMaxDynamicSharedMemorySize, CMB_SMEM);
    cudaFuncSetAttribute((const void*)gemm_mean<true>,
                         cudaFuncAttributeMaxDynamicSharedMemorySize, CMB_SMEM);
    cudaFuncSetAttribute((const void*)gemm_mean<false>,
                         cudaFuncAttributeMaxDynamicSharedMemorySize, CMB_SMEM);

    // side stream + events, created per call, never destroyed (host-side only;
    // destroying a capture-participating stream before EndCapture invalidates capture)
    cudaStream_t sB;
    cudaStreamCreateWithFlags(&sB, cudaStreamNonBlocking);
    cudaEvent_t evRoot, evF1, evF2, evB0, evB1, evB2;
    cudaEventCreateWithFlags(&evRoot, cudaEventDisableTiming);
    cudaEventCreateWithFlags(&evF1, cudaEventDisableTiming);
    cudaEventCreateWithFlags(&evF2, cudaEventDisableTiming);
    cudaEventCreateWithFlags(&evB0, cudaEventDisableTiming);
    cudaEventCreateWithFlags(&evB1, cudaEventDisableTiming);
    cudaEventCreateWithFlags(&evB2, cudaEventDisableTiming);

    int aggB = (n + 7) / 8;
    int cmbB = (n + 127) / 128;

    // fork: side stream does wsplit + layer-0 self-GEMM while main does CSR build
    cudaMemsetAsync(degi_p, 0, n * sizeof(int));
    cudaEventRecord(evRoot, 0);
    cudaStreamWaitEvent(sB, evRoot, 0);

    wsplit_kernel<<<(6 * 128 * 128 + 255) / 256, 256, 0, sB>>>(wl0, wr0, wl1, wr1, wl2, wr2);
    gemm_self<<<cmbB, 256, CMB_SMEM, sB>>>(x, wthi_p + 16384, wtlo_p + 16384, b0, tmp_p, n);
    cudaEventRecord(evB0, sB);

    count_deg<<<(E + 255) / 256, 256>>>(ei, E);
    scan_kernel<<<1, 1024>>>(n);
    fill_csr<<<(E + 255) / 256, 256>>>(ei, E);

    // layer 0
    aggregate_kernel<<<aggB, 256>>>(x, n);
    cudaStreamWaitEvent(0, evB0, 0);
    gemm_mean<true><<<cmbB, 256, CMB_SMEM>>>(wthi_p, wtlo_p, tmp_p, ha_p, n);

    // layer 1: fork self(ha)@Wr1 against aggregate(ha)
    cudaEventRecord(evF1, 0);
    cudaStreamWaitEvent(sB, evF1, 0);
    gemm_self<<<cmbB, 256, CMB_SMEM, sB>>>(ha_p, wthi_p + 3 * 16384, wtlo_p + 3 * 16384, b1, tmp_p, n);
    cudaEventRecord(evB1, sB);
    aggregate_kernel<<<aggB, 256>>>(ha_p, n);
    cudaStreamWaitEvent(0, evB1, 0);
    gemm_mean<true><<<cmbB, 256, CMB_SMEM>>>(wthi_p + 2 * 16384, wtlo_p + 2 * 16384, tmp_p, hb_p, n);

    // layer 2
    cudaEventRecord(evF2, 0);
    cudaStreamWaitEvent(sB, evF2, 0);
    gemm_self<<<cmbB, 256, CMB_SMEM, sB>>>(hb_p, wthi_p + 5 * 16384, wtlo_p + 5 * 16384, b2, tmp_p, n);
    cudaEventRecord(evB2, sB);
    aggregate_kernel<<<aggB, 256>>>(hb_p, n);
    cudaStreamWaitEvent(0, evB2, 0);
    gemm_mean<false><<<cmbB, 256, CMB_SMEM>>>(wthi_p + 4 * 16384, wtlo_p + 4 * 16384, tmp_p, out, n);
}

// round 17
// speedup vs baseline: 1.5124x; 1.5124x over previous
#include <cuda_runtime.h>
#include <cuda_bf16.h>
#include <cstdint>

#define DD 128
#define MAXN 50000
#define MAXE 800000
#define SCAN_CHUNK 4096

// ---------------- device scratch ----------------
__device__ float g_mean[(size_t)MAXN * DD];
__device__ float g_ha[(size_t)MAXN * DD];
__device__ float g_hb[(size_t)MAXN * DD];
__device__ float g_invdeg[MAXN];
__device__ int   g_degi[MAXN];
__device__ int   g_rowstart[MAXN + 1];
__device__ int   g_cursor[MAXN];
__device__ int   g_csr[MAXE];
__device__ int   g_blocksum[32];
__device__ int   g_blockoff[32];
// pre-split, transposed weights: [mat][n*128 + k], mat = 2*layer + {0:Wl,1:Wr}
__device__ __nv_bfloat16 g_wthi[6 * 128 * 128];
__device__ __nv_bfloat16 g_wtlo[6 * 128 * 128];

// ---------------- helpers ----------------
static __device__ __forceinline__ uint32_t smem_u32(const void* p) {
    uint32_t a;
    asm("{ .reg .u64 t; cvta.to.shared.u64 t, %1; cvt.u32.u64 %0, t; }" : "=r"(a) : "l"(p));
    return a;
}
static __device__ __forceinline__ void ldsm_x4(uint32_t* r, uint32_t addr) {
    asm volatile("ldmatrix.sync.aligned.m8n8.x4.shared.b16 {%0,%1,%2,%3}, [%4];"
                 : "=r"(r[0]), "=r"(r[1]), "=r"(r[2]), "=r"(r[3]) : "r"(addr));
}
static __device__ __forceinline__ void mma16816(float* c, const uint32_t* a, const uint32_t* b) {
    asm volatile("mma.sync.aligned.m16n8k16.row.col.f32.bf16.bf16.f32 "
                 "{%0,%1,%2,%3}, {%4,%5,%6,%7}, {%8,%9}, {%0,%1,%2,%3};"
                 : "+f"(c[0]), "+f"(c[1]), "+f"(c[2]), "+f"(c[3])
                 : "r"(a[0]), "r"(a[1]), "r"(a[2]), "r"(a[3]), "r"(b[0]), "r"(b[1]));
}

// ---------------- CSR construction (degi zeroed by cudaMemsetAsync) ----------------
__global__ void count_deg(const int* __restrict__ ei, int E) {
    int e = blockIdx.x * blockDim.x + threadIdx.x;
    if (e < E) atomicAdd(&g_degi[ei[E + e]], 1);
}

// ---- 3-phase parallel exclusive scan of degi ----
// phase1: per-block (4096-chunk) totals
__global__ void scan_phase1(int n) {
    __shared__ int wsum[32];
    int b = blockIdx.x, t = threadIdx.x, lane = t & 31, w = t >> 5;
    int i0 = b * SCAN_CHUNK + t * 4;
    int v = 0;
    if (i0 + 3 < n) {
        int4 q = *(const int4*)(g_degi + i0);
        v = q.x + q.y + q.z + q.w;
    } else {
        for (int j = 0; j < 4 && i0 + j < n; j++) v += g_degi[i0 + j];
    }
    #pragma unroll
    for (int off = 16; off > 0; off >>= 1)
        v += __shfl_down_sync(0xFFFFFFFFu, v, off);
    if (lane == 0) wsum[w] = v;
    __syncthreads();
    if (w == 0) {
        int s = wsum[lane];
        #pragma unroll
        for (int off = 16; off > 0; off >>= 1)
            s += __shfl_down_sync(0xFFFFFFFFu, s, off);
        if (lane == 0) g_blocksum[b] = s;
    }
}
// phase2: 1 warp scans block sums (exclusive)
__global__ void scan_phase2(int nb) {
    int t = threadIdx.x;
    int v = (t < nb) ? g_blocksum[t] : 0;
    int x = v;
    #pragma unroll
    for (int off = 1; off < 32; off <<= 1) {
        int y = __shfl_up_sync(0xFFFFFFFFu, x, off);
        if (t >= off) x += y;
    }
    if (t < nb) g_blockoff[t] = x - v;
    if (t == 0) g_rowstart[0] = 0;
}
// phase3: per-block local scan + block offset -> rowstart, cursor, invdeg
__global__ void scan_phase3(int n) {
    __shared__ int warp_sums[32];
    int b = blockIdx.x, t = threadIdx.x, lane = t & 31, w = t >> 5;
    int i0 = b * SCAN_CHUNK + t * 4;
    int v0 = 0, v1 = 0, v2 = 0, v3 = 0;
    if (i0 + 3 < n) {
        int4 q = *(const int4*)(g_degi + i0);
        v0 = q.x; v1 = q.y; v2 = q.z; v3 = q.w;
    } else {
        if (i0 < n)     v0 = g_degi[i0];
        if (i0 + 1 < n) v1 = g_degi[i0 + 1];
        if (i0 + 2 < n) v2 = g_degi[i0 + 2];
    }
    int v = v0 + v1 + v2 + v3;
    int x = v;
    #pragma unroll
    for (int off = 1; off < 32; off <<= 1) {
        int y = __shfl_up_sync(0xFFFFFFFFu, x, off);
        if (lane >= off) x += y;
    }
    if (lane == 31) warp_sums[w] = x;
    __syncthreads();
    if (w == 0) {
        int s = warp_sums[lane];
        #pragma unroll
        for (int off = 1; off < 32; off <<= 1) {
            int y = __shfl_up_sync(0xFFFFFFFFu, s, off);
            if (lane >= off) s += y;
        }
        warp_sums[lane] = s;
    }
    __syncthreads();
    int excl = (x - v) + (w > 0 ? warp_sums[w - 1] : 0) + g_blockoff[b];
    int p0 = excl + v0, p1 = p0 + v1, p2 = p1 + v2, p3 = p2 + v3;
    if (i0 < n)     { g_rowstart[i0 + 1] = p0; g_cursor[i0]     = excl; g_invdeg[i0]     = 1.0f / (float)(v0 > 0 ? v0 : 1); }
    if (i0 + 1 < n) { g_rowstart[i0 + 2] = p1; g_cursor[i0 + 1] = p0;   g_invdeg[i0 + 1] = 1.0f / (float)(v1 > 0 ? v1 : 1); }
    if (i0 + 2 < n) { g_rowstart[i0 + 3] = p2; g_cursor[i0 + 2] = p1;   g_invdeg[i0 + 2] = 1.0f / (float)(v2 > 0 ? v2 : 1); }
    if (i0 + 3 < n) { g_rowstart[i0 + 4] = p3; g_cursor[i0 + 3] = p2;   g_invdeg[i0 + 3] = 1.0f / (float)(v3 > 0 ? v3 : 1); }
}

__global__ void fill_csr(const int* __restrict__ ei, int E) {
    int e = blockIdx.x * blockDim.x + threadIdx.x;
    if (e < E) {
        int s = ei[e];
        int d = ei[E + e];
        int p = atomicAdd(&g_cursor[d], 1);   // cursor pre-seeded with rowstart
        g_csr[p] = s;
    }
}

// ---------------- weight pre-split (transpose + bf16 hi/lo) ----------------
__global__ void wsplit_kernel(const float* w0, const float* w1, const float* w2,
                              const float* w3, const float* w4, const float* w5) {
    int id = blockIdx.x * blockDim.x + threadIdx.x;
    if (id >= 6 * 128 * 128) return;
    int mat = id >> 14, rem = id & 16383;
    int nn = rem >> 7, kk = rem & 127;
    const float* w;
    switch (mat) {
        case 0: w = w0; break; case 1: w = w1; break; case 2: w = w2; break;
        case 3: w = w3; break; case 4: w = w4; break; default: w = w5; break;
    }
    float v = w[kk * 128 + nn];           // transpose: wt[n][k] = w[k][n]
    __nv_bfloat16 hi = __float2bfloat16(v);
    g_wthi[id] = hi;
    g_wtlo[id] = __float2bfloat16(v - __bfloat162float(hi));
}

// ---------------- aggregation: warp per node, gather-only (proven config) ----------------
__global__ void aggregate_kernel(const float* __restrict__ hin, int n) {
    int gw = (blockIdx.x * blockDim.x + threadIdx.x) >> 5;
    int lane = threadIdx.x & 31;
    if (gw >= n) return;
    int s0 = g_rowstart[gw], s1 = g_rowstart[gw + 1];
    float ax = 0.f, ay = 0.f, az = 0.f, aw = 0.f;
    int i = s0;
    for (; i + 4 <= s1; i += 4) {
        int e0 = g_csr[i], e1 = g_csr[i + 1], e2 = g_csr[i + 2], e3 = g_csr[i + 3];
        float4 v0 = *(const float4*)(hin + (size_t)e0 * DD + lane * 4);
        float4 v1 = *(const float4*)(hin + (size_t)e1 * DD + lane * 4);
        float4 v2 = *(const float4*)(hin + (size_t)e2 * DD + lane * 4);
        float4 v3 = *(const float4*)(hin + (size_t)e3 * DD + lane * 4);
        ax += (v0.x + v1.x) + (v2.x + v3.x);
        ay += (v0.y + v1.y) + (v2.y + v3.y);
        az += (v0.z + v1.z) + (v2.z + v3.z);
        aw += (v0.w + v1.w) + (v2.w + v3.w);
    }
    for (; i < s1; i++) {
        int e0 = g_csr[i];
        float4 v = *(const float4*)(hin + (size_t)e0 * DD + lane * 4);
        ax += v.x; ay += v.y; az += v.z; aw += v.w;
    }
    float inv = g_invdeg[gw];
    float4 r;
    r.x = ax * inv; r.y = ay * inv; r.z = az * inv; r.w = aw * inv;
    *(float4*)(g_mean + (size_t)gw * DD + lane * 4) = r;
}

// ---------------- mma.sync combine: out = mean @ Wl + h @ Wr + b (+ReLU) ----------------
// 3-term bf16 split: A@B ~= Ahi@Bhi + Ahi@Blo + Alo@Bhi  (residual ~2^-16)
// Dual GEMM = K-concat: chunk0 = (mean, Wl), chunk1 = (h, Wr), accumulators persist.
// R5-proven config: CTA 128x128, 8 warps (4x2), warp tile 32x64, 1 CTA/SM.
#define KPAD_B 272                       // 136 bf16/row = 17 x 16B -> ldmatrix conflict-free
#define A_HI 0
#define A_LO (128 * KPAD_B)
#define B_HI (2 * 128 * KPAD_B)
#define B_LO (3 * 128 * KPAD_B)
#define CMB_SMEM (4 * 128 * KPAD_B)      // 139,264 bytes

template <bool RELU>
__global__ __launch_bounds__(256, 1) void combine_mma(
    const float* __restrict__ mean, const float* __restrict__ h,
    const __nv_bfloat16* __restrict__ wthi, const __nv_bfloat16* __restrict__ wtlo,
    const float* __restrict__ bias, float* __restrict__ out, int n)
{
    extern __shared__ char smem[];
    uint32_t sb = smem_u32(smem);
    int tid = threadIdx.x, wid = tid >> 5, lane = tid & 31;
    int row0 = blockIdx.x * 128;
    int wR = wid >> 1, wC = wid & 1;

    float acc[2][8][4];
    #pragma unroll
    for (int mi = 0; mi < 2; mi++)
        #pragma unroll
        for (int nj = 0; nj < 8; nj++)
            #pragma unroll
            for (int q = 0; q < 4; q++) acc[mi][nj][q] = 0.f;

    int a_row  = wR * 32 + (lane & 15);
    int a_koff = (lane >> 4) * 8;
    int b_nrow = wC * 64 + (lane & 7) + ((lane >> 4) << 3);
    int b_koff = ((lane >> 3) & 1) * 8;

    #pragma unroll
    for (int chunk = 0; chunk < 2; chunk++) {
        const float* src = chunk ? h : mean;
        for (int idx = tid; idx < 4096; idx += 256) {
            int r = idx >> 5, kq = idx & 31;
            int row = row0 + r;
            float4 v = {0.f, 0.f, 0.f, 0.f};
            if (row < n) v = *(const float4*)(src + (size_t)row * DD + kq * 4);
            __nv_bfloat16 hx = __float2bfloat16(v.x), hy = __float2bfloat16(v.y);
            __nv_bfloat16 hz = __float2bfloat16(v.z), hw = __float2bfloat16(v.w);
            __nv_bfloat162 h01, h23, l01, l23;
            h01.x = hx; h01.y = hy; h23.x = hz; h23.y = hw;
            l01.x = __float2bfloat16(v.x - __bfloat162float(hx));
            l01.y = __float2bfloat16(v.y - __bfloat162float(hy));
            l23.x = __float2bfloat16(v.z - __bfloat162float(hz));
            l23.y = __float2bfloat16(v.w - __bfloat162float(hw));
            uint2 hp, lp;
            hp.x = *(uint32_t*)&h01; hp.y = *(uint32_t*)&h23;
            lp.x = *(uint32_t*)&l01; lp.y = *(uint32_t*)&l23;
            *(uint2*)(smem + A_HI + r * KPAD_B + kq * 8) = hp;
            *(uint2*)(smem + A_LO + r * KPAD_B + kq * 8) = lp;
        }
        const __nv_bfloat16* bh = wthi + chunk * 16384;
        const __nv_bfloat16* bl = wtlo + chunk * 16384;
        for (int idx = tid; idx < 2048; idx += 256) {
            int nr = idx >> 4, kg = idx & 15;
            *(uint4*)(smem + B_HI + nr * KPAD_B + kg * 16) = *(const uint4*)(bh + nr * 128 + kg * 8);
            *(uint4*)(smem + B_LO + nr * KPAD_B + kg * 16) = *(const uint4*)(bl + nr * 128 + kg * 8);
        }
        __syncthreads();

        #pragma unroll
        for (int ks = 0; ks < 8; ks++) {
            int k0 = ks * 16;
            uint32_t aF[2][2][4];
            #pragma unroll
            for (int p = 0; p < 2; p++)
                #pragma unroll
                for (int mi = 0; mi < 2; mi++)
                    ldsm_x4(aF[p][mi],
                            sb + (p ? A_LO : A_HI) + (a_row + mi * 16) * KPAD_B + (k0 + a_koff) * 2);
            uint32_t bF[2][4][4];
            #pragma unroll
            for (int p = 0; p < 2; p++)
                #pragma unroll
                for (int gj = 0; gj < 4; gj++)
                    ldsm_x4(bF[p][gj],
                            sb + (p ? B_LO : B_HI) + (b_nrow + gj * 16) * KPAD_B + (k0 + b_koff) * 2);
            #pragma unroll
            for (int mi = 0; mi < 2; mi++)
                #pragma unroll
                for (int nj = 0; nj < 8; nj++) {
                    int gj = nj >> 1, s = (nj & 1) * 2;
                    mma16816(acc[mi][nj], aF[0][mi], &bF[0][gj][s]);  // hi*hi
                    mma16816(acc[mi][nj], aF[0][mi], &bF[1][gj][s]);  // hi*lo
                    mma16816(acc[mi][nj], aF[1][mi], &bF[0][gj][s]);  // lo*hi
                }
        }
        __syncthreads();
    }

    #pragma unroll
    for (int mi = 0; mi < 2; mi++) {
        int r0a = row0 + wR * 32 + mi * 16 + (lane >> 2);
        #pragma unroll
        for (int nj = 0; nj < 8; nj++) {
            int col = wC * 64 + nj * 8 + (lane & 3) * 2;
            float2 bb = *(const float2*)(bias + col);
            float2 v0, v1;
            v0.x = acc[mi][nj][0] + bb.x; v0.y = acc[mi][nj][1] + bb.y;
            v1.x = acc[mi][nj][2] + bb.x; v1.y = acc[mi][nj][3] + bb.y;
            if (RELU) {
                v0.x = fmaxf(v0.x, 0.f); v0.y = fmaxf(v0.y, 0.f);
                v1.x = fmaxf(v1.x, 0.f); v1.y = fmaxf(v1.y, 0.f);
            }
            if (r0a < n)     *(float2*)(out + (size_t)r0a * DD + col) = v0;
            if (r0a + 8 < n) *(float2*)(out + (size_t)(r0a + 8) * DD + col) = v1;
        }
    }
}

// ---------------- launch (single stream, serial: R14 structure + parallel scan) ----------------
extern "C" void kernel_launch(void* const* d_in, const int* in_sizes, int n_in,
                              void* d_out, int out_size) {
    const float* x   = (const float*)d_in[0];
    const int*   ei  = (const int*)d_in[1];
    const float* wl0 = (const float*)d_in[2];
    const float* wr0 = (const float*)d_in[3];
    const float* b0  = (const float*)d_in[4];
    const float* wl1 = (const float*)d_in[5];
    const float* wr1 = (const float*)d_in[6];
    const float* b1  = (const float*)d_in[7];
    const float* wl2 = (const float*)d_in[8];
    const float* wr2 = (const float*)d_in[9];
    const float* b2  = (const float*)d_in[10];
    float* out = (float*)d_out;

    int n = in_sizes[0] / DD;
    int E = in_sizes[1] / 2;

    float *mean_p, *ha_p, *hb_p;
    int* degi_p;
    __nv_bfloat16 *wthi_p, *wtlo_p;
    cudaGetSymbolAddress((void**)&mean_p, g_mean);
    cudaGetSymbolAddress((void**)&ha_p, g_ha);
    cudaGetSymbolAddress((void**)&hb_p, g_hb);
    cudaGetSymbolAddress((void**)&degi_p, g_degi);
    cudaGetSymbolAddress((void**)&wthi_p, g_wthi);
    cudaGetSymbolAddress((void**)&wtlo_p, g_wtlo);

    cudaFuncSetAttribute((const void*)combine_mma<true>,
                         cudaFuncAttributeMaxDynamicSharedMemorySize, CMB_SMEM);
    cudaFuncSetAttribute((const void*)combine_mma<false>,
                         cudaFuncAttributeMaxDynamicSharedMemorySize, CMB_SMEM);

    int aggB = (n + 7) / 8;
    int cmbB = (n + 127) / 128;
    int nb = (n + SCAN_CHUNK - 1) / SCAN_CHUNK;

    // prep: memset + CSR chain with parallel 3-phase scan
    cudaMemsetAsync(degi_p, 0, n * sizeof(int));
    count_deg<<<(E + 255) / 256, 256>>>(ei, E);                 // k0
    scan_phase1<<<nb, 1024>>>(n);                               // k1
    scan_phase2<<<1, 32>>>(nb);                                 // k2
    scan_phase3<<<nb, 1024>>>(n);                               // k3 <- ncu target
    fill_csr<<<(E + 255) / 256, 256>>>(ei, E);                  // k4

    // layer 0: x -> ha (relu)
    aggregate_kernel<<<aggB, 256>>>(x, n);
    wsplit_kernel<<<(6 * 128 * 128 + 255) / 256, 256>>>(wl0, wr0, wl1, wr1, wl2, wr2);
    combine_mma<true><<<cmbB, 256, CMB_SMEM>>>(mean_p, x, wthi_p, wtlo_p, b0, ha_p, n);

    // layer 1: ha -> hb (relu)
    aggregate_kernel<<<aggB, 256>>>(ha_p, n);
    combine_mma<true><<<cmbB, 256, CMB_SMEM>>>(mean_p, ha_p, wthi_p + 2 * 16384, wtlo_p + 2 * 16384, b1, hb_p, n);

    // layer 2: hb -> out (no relu)
    aggregate_kernel<<<aggB, 256>>>(hb_p, n);
    combine_mma<false><<<cmbB, 256, CMB_SMEM>>>(mean_p, hb_p, wthi_p + 4 * 16384, wtlo_p + 4 * 16384, b2, out, n);
}